// round 12
// baseline (speedup 1.0000x reference)
#include <cuda_runtime.h>
#include <cuda_fp16.h>
#include <math.h>
#include <stdint.h>

typedef unsigned int u32;

// Fixed dataset shapes: M=4096, K=2048, N=32000
#define MAX_M 4096
#define MAX_K 2048
#define MAX_V 32000

// Static device scratch (allocation-free rule)
__device__ __half g_XH[(size_t)MAX_M * MAX_K];   // x rounded to fp16
__device__ __half g_WD[(size_t)MAX_V * MAX_K];   // dequantized weights in fp16

// ---------------- PTX helpers ----------------

static __device__ __forceinline__ u32 smem_u32(const void* p) {
    u32 a;
    asm("{ .reg .u64 t; cvta.to.shared.u64 t, %1; cvt.u32.u64 %0, t; }"
        : "=r"(a) : "l"(p));
    return a;
}

static __device__ __forceinline__ void cp16(u32 d, const void* g) {
    asm volatile("cp.async.cg.shared.global [%0], [%1], 16;"
                 :: "r"(d), "l"(g) : "memory");
}
static __device__ __forceinline__ void cp_commit() {
    asm volatile("cp.async.commit_group;" ::: "memory");
}
static __device__ __forceinline__ void cp_wait1() {
    asm volatile("cp.async.wait_group 1;" ::: "memory");
}

static __device__ __forceinline__ void ldsm4(u32 a, u32& r0, u32& r1, u32& r2, u32& r3) {
    asm volatile("ldmatrix.sync.aligned.m8n8.x4.shared.b16 {%0,%1,%2,%3}, [%4];"
                 : "=r"(r0), "=r"(r1), "=r"(r2), "=r"(r3) : "r"(a));
}

static __device__ __forceinline__ void mma16816(float* c,
                                                u32 a0, u32 a1, u32 a2, u32 a3,
                                                u32 b0, u32 b1) {
    asm volatile(
        "mma.sync.aligned.m16n8k16.row.col.f32.f16.f16.f32 "
        "{%0,%1,%2,%3}, {%4,%5,%6,%7}, {%8,%9}, {%0,%1,%2,%3};"
        : "+f"(c[0]), "+f"(c[1]), "+f"(c[2]), "+f"(c[3])
        : "r"(a0), "r"(a1), "r"(a2), "r"(a3), "r"(b0), "r"(b1));
}

// Full SW128 swizzle for 128B rows (BK=64 f16): conflict-free STS.128 + ldmatrix.
static __device__ __forceinline__ u32 swz(int row, int chunk) {
    return (u32)(row * 128 + ((chunk ^ (row & 7)) << 4));
}

// ---------------- Pre-pass kernels ----------------

__global__ void prep_x_kernel(const float* __restrict__ X, int total4) {
    int i = blockIdx.x * 256 + threadIdx.x;
    if (i >= total4) return;
    float4 v = ((const float4*)X)[i];
    __half h[4];
    h[0] = __float2half_rn(v.x);
    h[1] = __float2half_rn(v.y);
    h[2] = __float2half_rn(v.z);
    h[3] = __float2half_rn(v.w);
    ((uint2*)g_XH)[i] = *(uint2*)h;
}

// Full dequant: w = (q - 127.5) * absmax/127.5, rounded to fp16. 8 elems/thread.
__global__ void prep_w_kernel(const int* __restrict__ Q,
                              const float* __restrict__ AM,
                              int total8, int kdiv8, int nblk) {
    int i = blockIdx.x * 256 + threadIdx.x;
    if (i >= total8) return;
    int row = i / kdiv8;
    int c8 = i - row * kdiv8;
    int kblk = (c8 * 8) >> 8;
    float s = AM[(size_t)row * nblk + kblk] * (1.0f / 127.5f);
    int4 a = ((const int4*)Q)[2 * i];
    int4 b = ((const int4*)Q)[2 * i + 1];
    __half h[8];
    h[0] = __float2half_rn(((float)a.x - 127.5f) * s);
    h[1] = __float2half_rn(((float)a.y - 127.5f) * s);
    h[2] = __float2half_rn(((float)a.z - 127.5f) * s);
    h[3] = __float2half_rn(((float)a.w - 127.5f) * s);
    h[4] = __float2half_rn(((float)b.x - 127.5f) * s);
    h[5] = __float2half_rn(((float)b.y - 127.5f) * s);
    h[6] = __float2half_rn(((float)b.z - 127.5f) * s);
    h[7] = __float2half_rn(((float)b.w - 127.5f) * s);
    ((uint4*)g_WD)[i] = *(uint4*)h;
}

// ---------------- Main GEMM ----------------
// C[M,N] = X(fp16) * W(fp16)^T, fp32-accumulate HMMA.
// CTA 128x256, BK=64, 8 warps (2m x 4n), warp tile 64x64 (square),
// 256 threads, 3-stage cp.async, 1 CTA/SM (full smem crossbar per CTA).

#define BM 128
#define BN 256
#define BK 64
#define THREADS 256
#define TILE_XB (BM * 128)         // 16 KB X [128][64] f16
#define TILE_WB (BN * 128)         // 32 KB W [256][64] f16
#define STAGE_B (TILE_XB + TILE_WB)   // 48 KB
#define NSTAGE 3
#define SMEM_B (NSTAGE * STAGE_B)  // 144 KB

__global__ __launch_bounds__(THREADS, 1)
void gemm_hmma(float* __restrict__ C, int M, int N, int K) {
    extern __shared__ char sm[];
    const u32 sb = smem_u32(sm);
    const int tid = threadIdx.x;
    const int wid = tid >> 5;
    const int lane = tid & 31;
    const int m0 = blockIdx.x * BM;
    const int n0 = blockIdx.y * BN;
    const int warp_m = wid >> 2;      // 0..1 (64 rows each)
    const int warp_n = wid & 3;       // 0..3 (64 cols each)

    const size_t baseX = (size_t)m0 * K;
    const size_t baseW = (size_t)n0 * K;

    // cp.async mapping: 8 threads per 128B row; 32 rows per pass
    const int lrow = tid >> 3;        // 0..31
    const int lchk = tid & 7;         // 0..7

    // A ldmatrix lane decode (x4: m16 x k16 per mi)
    const int matA = lane >> 3;
    const int rowA_base = warp_m * 64 + ((matA & 1) << 3) + (lane & 7);
    const int cA_sel = matA >> 1;
    // B ldmatrix lane decode (x4 covers 2 nj x 2 k-halves)
    const int matB = lane >> 3;
    const int rowB_base = warp_n * 64 + ((matB >> 1) << 3) + (lane & 7);
    const int cB_sel = matB & 1;

    float fin[4][8][4];
#pragma unroll
    for (int i = 0; i < 4; i++)
#pragma unroll
        for (int j = 0; j < 8; j++)
#pragma unroll
            for (int e = 0; e < 4; e++) fin[i][j][e] = 0.0f;

    const int NK = K / BK;   // 32

    // ---- prologue: prefetch stages 0,1 ----
#pragma unroll
    for (int ps = 0; ps < NSTAGE - 1; ps++) {
        const int k0 = ps * BK;
        const u32 st = sb + ps * STAGE_B;
#pragma unroll
        for (int t = 0; t < 4; t++) {   // X: 128 rows
            int row = lrow + t * 32;
            size_t gx = baseX + (size_t)row * K + k0 + lchk * 8;
            cp16(st + swz(row, lchk), g_XH + gx);
        }
#pragma unroll
        for (int t = 0; t < 8; t++) {   // W: 256 rows
            int row = lrow + t * 32;
            size_t gw = baseW + (size_t)row * K + k0 + lchk * 8;
            cp16(st + TILE_XB + swz(row, lchk), g_WD + gw);
        }
        cp_commit();
    }

    for (int kt = 0; kt < NK; kt++) {
        const int s = kt % NSTAGE;

        cp_wait1();           // stage kt landed (in-order group completion)
        __syncthreads();      // stage kt visible; stage kt-1 reads complete

        // ---- prefetch stage kt+2 into buffer (kt-1)%3 (now safe) ----
        if (kt + NSTAGE - 1 < NK) {
            const int k0 = (kt + NSTAGE - 1) * BK;
            const u32 st = sb + ((kt + NSTAGE - 1) % NSTAGE) * STAGE_B;
#pragma unroll
            for (int t = 0; t < 4; t++) {
                int row = lrow + t * 32;
                size_t gx = baseX + (size_t)row * K + k0 + lchk * 8;
                cp16(st + swz(row, lchk), g_XH + gx);
            }
#pragma unroll
            for (int t = 0; t < 8; t++) {
                int row = lrow + t * 32;
                size_t gw = baseW + (size_t)row * K + k0 + lchk * 8;
                cp16(st + TILE_XB + swz(row, lchk), g_WD + gw);
            }
        }
        cp_commit();          // unconditional: uniform group accounting

        // ---- compute stage s: 4 k16 sub-steps ----
        const u32 stA = sb + s * STAGE_B;
        const u32 stB = stA + TILE_XB;

#pragma unroll
        for (int ks = 0; ks < 4; ks++) {
            // B frags: 8 nj; each ldsm4 covers 2 nj x 2 k-halves
            u32 bq[8][2];
#pragma unroll
            for (int njp = 0; njp < 4; njp++) {
                u32 off = swz(rowB_base + njp * 16, ks * 2 + cB_sel);
                ldsm4(stB + off, bq[njp * 2][0], bq[njp * 2][1],
                      bq[njp * 2 + 1][0], bq[njp * 2 + 1][1]);
            }
#pragma unroll
            for (int mi = 0; mi < 4; mi++) {
                u32 off = swz(rowA_base + mi * 16, ks * 2 + cA_sel);
                u32 a0, a1, a2, a3;
                ldsm4(stA + off, a0, a1, a2, a3);
#pragma unroll
                for (int nj = 0; nj < 8; nj++)
                    mma16816(fin[mi][nj], a0, a1, a2, a3, bq[nj][0], bq[nj][1]);
            }
        }
    }

    // ---- epilogue ----
    const int er = m0 + warp_m * 64 + (lane >> 2);
    const int ec = n0 + warp_n * 64 + (lane & 3) * 2;
#pragma unroll
    for (int mi = 0; mi < 4; mi++) {
#pragma unroll
        for (int nj = 0; nj < 8; nj++) {
            float* p0 = C + (size_t)(er + mi * 16) * N + ec + nj * 8;
            float* p1 = C + (size_t)(er + mi * 16 + 8) * N + ec + nj * 8;
            *(float2*)p0 = make_float2(fin[mi][nj][0], fin[mi][nj][1]);
            *(float2*)p1 = make_float2(fin[mi][nj][2], fin[mi][nj][3]);
        }
    }
}

// ---------------- launch ----------------

extern "C" void kernel_launch(void* const* d_in, const int* in_sizes, int n_in,
                              void* d_out, int out_size) {
    const float* X  = (const float*)d_in[0];
    const int*   Q  = (const int*)d_in[1];
    const float* AM = (const float*)d_in[2];

    double s0 = (double)in_sizes[0];
    double s1 = (double)in_sizes[1];
    double so = (double)out_size;
    int K = (int)(sqrt(s0 * s1 / so) + 0.5);
    int M = (int)(s0 / K + 0.5);
    int N = (int)(s1 / K + 0.5);
    int nblk = K >> 8;

    int xt4 = (M * K) / 4;
    prep_x_kernel<<<(xt4 + 255) / 256, 256>>>(X, xt4);
    int wt8 = (int)(((long long)N * K) / 8);
    prep_w_kernel<<<(wt8 + 255) / 256, 256>>>(Q, AM, wt8, K / 8, nblk);

    cudaFuncSetAttribute(gemm_hmma, cudaFuncAttributeMaxDynamicSharedMemorySize, SMEM_B);
    dim3 grid(M / BM, N / BN);   // m fastest: W n-stripe shared via L2 within a wave
    gemm_hmma<<<grid, THREADS, SMEM_B>>>((float*)d_out, M, N, K);
}

// round 13
// speedup vs baseline: 1.0143x; 1.0143x over previous
#include <cuda_runtime.h>
#include <cuda_fp16.h>
#include <math.h>
#include <stdint.h>

typedef unsigned int u32;

// Fixed dataset shapes: M=4096, K=2048, N=32000
#define MAX_M 4096
#define MAX_K 2048
#define MAX_V 32000

// Static device scratch (allocation-free rule)
__device__ __half g_XH[(size_t)MAX_M * MAX_K];   // x rounded to fp16
__device__ __half g_WD[(size_t)MAX_V * MAX_K];   // dequantized weights in fp16

// ---------------- PTX helpers ----------------

static __device__ __forceinline__ u32 smem_u32(const void* p) {
    u32 a;
    asm("{ .reg .u64 t; cvta.to.shared.u64 t, %1; cvt.u32.u64 %0, t; }"
        : "=r"(a) : "l"(p));
    return a;
}

static __device__ __forceinline__ void cp16(u32 d, const void* g) {
    asm volatile("cp.async.cg.shared.global [%0], [%1], 16;"
                 :: "r"(d), "l"(g) : "memory");
}
static __device__ __forceinline__ void cp_commit() {
    asm volatile("cp.async.commit_group;" ::: "memory");
}
static __device__ __forceinline__ void cp_wait1() {
    asm volatile("cp.async.wait_group 1;" ::: "memory");
}

static __device__ __forceinline__ void ldsm4(u32 a, u32& r0, u32& r1, u32& r2, u32& r3) {
    asm volatile("ldmatrix.sync.aligned.m8n8.x4.shared.b16 {%0,%1,%2,%3}, [%4];"
                 : "=r"(r0), "=r"(r1), "=r"(r2), "=r"(r3) : "r"(a));
}

static __device__ __forceinline__ void mma16816(float* c,
                                                u32 a0, u32 a1, u32 a2, u32 a3,
                                                u32 b0, u32 b1) {
    asm volatile(
        "mma.sync.aligned.m16n8k16.row.col.f32.f16.f16.f32 "
        "{%0,%1,%2,%3}, {%4,%5,%6,%7}, {%8,%9}, {%0,%1,%2,%3};"
        : "+f"(c[0]), "+f"(c[1]), "+f"(c[2]), "+f"(c[3])
        : "r"(a0), "r"(a1), "r"(a2), "r"(a3), "r"(b0), "r"(b1));
}

// Full SW128 swizzle for 128B rows (BK=64 f16): conflict-free STS.128 + ldmatrix.
static __device__ __forceinline__ u32 swz(int row, int chunk) {
    return (u32)(row * 128 + ((chunk ^ (row & 7)) << 4));
}

// ---------------- Pre-pass kernels ----------------

__global__ void prep_x_kernel(const float* __restrict__ X, int total4) {
    int i = blockIdx.x * 256 + threadIdx.x;
    if (i >= total4) return;
    float4 v = ((const float4*)X)[i];
    __half h[4];
    h[0] = __float2half_rn(v.x);
    h[1] = __float2half_rn(v.y);
    h[2] = __float2half_rn(v.z);
    h[3] = __float2half_rn(v.w);
    ((uint2*)g_XH)[i] = *(uint2*)h;
}

// Full dequant: w = (q - 127.5) * absmax/127.5, rounded to fp16. 8 elems/thread.
__global__ void prep_w_kernel(const int* __restrict__ Q,
                              const float* __restrict__ AM,
                              int total8, int kdiv8, int nblk) {
    int i = blockIdx.x * 256 + threadIdx.x;
    if (i >= total8) return;
    int row = i / kdiv8;
    int c8 = i - row * kdiv8;
    int kblk = (c8 * 8) >> 8;
    float s = AM[(size_t)row * nblk + kblk] * (1.0f / 127.5f);
    int4 a = ((const int4*)Q)[2 * i];
    int4 b = ((const int4*)Q)[2 * i + 1];
    __half h[8];
    h[0] = __float2half_rn(((float)a.x - 127.5f) * s);
    h[1] = __float2half_rn(((float)a.y - 127.5f) * s);
    h[2] = __float2half_rn(((float)a.z - 127.5f) * s);
    h[3] = __float2half_rn(((float)a.w - 127.5f) * s);
    h[4] = __float2half_rn(((float)b.x - 127.5f) * s);
    h[5] = __float2half_rn(((float)b.y - 127.5f) * s);
    h[6] = __float2half_rn(((float)b.z - 127.5f) * s);
    h[7] = __float2half_rn(((float)b.w - 127.5f) * s);
    ((uint4*)g_WD)[i] = *(uint4*)h;
}

// ---------------- Main GEMM ----------------
// C[M,N] = X(fp16) * W(fp16)^T, fp32-accumulate HMMA.
// Persistent CTAs: grid = 2*148, each walks tiles m-fastest.
// Per tile: CTA 128x128, BK=64, 4 warps (2m x 2n, 64x64 each),
// 128 threads, 3-stage cp.async, 2 CTAs/SM.

#define BM 128
#define BN 128
#define BK 64
#define THREADS 128
#define TILE_XB (BM * 128)         // 16 KB X [128][64] f16
#define TILE_WB (BN * 128)         // 16 KB W [128][64] f16
#define STAGE_B (TILE_XB + TILE_WB)   // 32 KB
#define NSTAGE 3
#define SMEM_B (NSTAGE * STAGE_B)  // 96 KB

__global__ __launch_bounds__(THREADS, 2)
void gemm_hmma(float* __restrict__ C, int M, int N, int K, int ntiles, int mtiles) {
    extern __shared__ char sm[];
    const u32 sb = smem_u32(sm);
    const int tid = threadIdx.x;
    const int wid = tid >> 5;
    const int lane = tid & 31;
    const int warp_m = wid >> 1;      // 0..1 (64 rows each)
    const int warp_n = wid & 1;       // 0..1 (64 cols each)

    // cp.async mapping: 8 threads per 128B row; 16 rows per pass, 8 passes/tile
    const int lrow = tid >> 3;        // 0..15
    const int lchk = tid & 7;         // 0..7

    // A ldmatrix lane decode (x4: m16 x k16 per mi)
    const int matA = lane >> 3;
    const int rowA_base = warp_m * 64 + ((matA & 1) << 3) + (lane & 7);
    const int cA_sel = matA >> 1;
    // B ldmatrix lane decode (x4 covers 2 nj x 2 k-halves)
    const int matB = lane >> 3;
    const int rowB_base = warp_n * 64 + ((matB >> 1) << 3) + (lane & 7);
    const int cB_sel = matB & 1;

    const int NK = K / BK;   // 32

    for (int tile = blockIdx.x; tile < ntiles; tile += gridDim.x) {
        const int mt = tile % mtiles;            // m fastest: wave shares W n-stripe
        const int nt = tile / mtiles;
        const int m0 = mt * BM;
        const int n0 = nt * BN;
        const size_t baseX = (size_t)m0 * K;
        const size_t baseW = (size_t)n0 * K;

        float fin[4][8][4];
#pragma unroll
        for (int i = 0; i < 4; i++)
#pragma unroll
            for (int j = 0; j < 8; j++)
#pragma unroll
                for (int e = 0; e < 4; e++) fin[i][j][e] = 0.0f;

        // ---- prologue: prefetch stages 0,1 ----
#pragma unroll
        for (int ps = 0; ps < NSTAGE - 1; ps++) {
            const int k0 = ps * BK;
            const u32 st = sb + ps * STAGE_B;
#pragma unroll
            for (int t = 0; t < 8; t++) {
                int row = lrow + t * 16;
                u32 sw = swz(row, lchk);
                size_t gx = baseX + (size_t)row * K + k0 + lchk * 8;
                size_t gw = baseW + (size_t)row * K + k0 + lchk * 8;
                cp16(st + sw, g_XH + gx);
                cp16(st + TILE_XB + sw, g_WD + gw);
            }
            cp_commit();
        }

        for (int kt = 0; kt < NK; kt++) {
            const int s = kt % NSTAGE;

            cp_wait1();           // stage kt landed (in-order group completion)
            __syncthreads();      // stage kt visible; stage kt-1 reads complete

            // ---- prefetch stage kt+2 into buffer (kt-1)%3 (now safe) ----
            if (kt + NSTAGE - 1 < NK) {
                const int k0 = (kt + NSTAGE - 1) * BK;
                const u32 st = sb + ((kt + NSTAGE - 1) % NSTAGE) * STAGE_B;
#pragma unroll
                for (int t = 0; t < 8; t++) {
                    int row = lrow + t * 16;
                    u32 sw = swz(row, lchk);
                    size_t gx = baseX + (size_t)row * K + k0 + lchk * 8;
                    size_t gw = baseW + (size_t)row * K + k0 + lchk * 8;
                    cp16(st + sw, g_XH + gx);
                    cp16(st + TILE_XB + sw, g_WD + gw);
                }
            }
            cp_commit();          // unconditional: uniform group accounting

            // ---- compute stage s: 4 k16 sub-steps ----
            const u32 stA = sb + s * STAGE_B;
            const u32 stB = stA + TILE_XB;

#pragma unroll
            for (int ks = 0; ks < 4; ks++) {
                u32 bq[8][2];
#pragma unroll
                for (int njp = 0; njp < 4; njp++) {
                    u32 off = swz(rowB_base + njp * 16, ks * 2 + cB_sel);
                    ldsm4(stB + off, bq[njp * 2][0], bq[njp * 2][1],
                          bq[njp * 2 + 1][0], bq[njp * 2 + 1][1]);
                }
#pragma unroll
                for (int mi = 0; mi < 4; mi++) {
                    u32 off = swz(rowA_base + mi * 16, ks * 2 + cA_sel);
                    u32 a0, a1, a2, a3;
                    ldsm4(stA + off, a0, a1, a2, a3);
#pragma unroll
                    for (int nj = 0; nj < 8; nj++)
                        mma16816(fin[mi][nj], a0, a1, a2, a3, bq[nj][0], bq[nj][1]);
                }
            }
        }

        // Guard stage buffers: lagging warps must finish the last stage reads
        // before any warp prefetches the next tile's prologue into them.
        __syncthreads();

        // ---- epilogue ----
        const int er = m0 + warp_m * 64 + (lane >> 2);
        const int ec = n0 + warp_n * 64 + (lane & 3) * 2;
#pragma unroll
        for (int mi = 0; mi < 4; mi++) {
#pragma unroll
            for (int nj = 0; nj < 8; nj++) {
                float* p0 = C + (size_t)(er + mi * 16) * N + ec + nj * 8;
                float* p1 = C + (size_t)(er + mi * 16 + 8) * N + ec + nj * 8;
                *(float2*)p0 = make_float2(fin[mi][nj][0], fin[mi][nj][1]);
                *(float2*)p1 = make_float2(fin[mi][nj][2], fin[mi][nj][3]);
            }
        }
    }
}

// ---------------- launch ----------------

extern "C" void kernel_launch(void* const* d_in, const int* in_sizes, int n_in,
                              void* d_out, int out_size) {
    const float* X  = (const float*)d_in[0];
    const int*   Q  = (const int*)d_in[1];
    const float* AM = (const float*)d_in[2];

    double s0 = (double)in_sizes[0];
    double s1 = (double)in_sizes[1];
    double so = (double)out_size;
    int K = (int)(sqrt(s0 * s1 / so) + 0.5);
    int M = (int)(s0 / K + 0.5);
    int N = (int)(s1 / K + 0.5);
    int nblk = K >> 8;

    int xt4 = (M * K) / 4;
    prep_x_kernel<<<(xt4 + 255) / 256, 256>>>(X, xt4);
    int wt8 = (int)(((long long)N * K) / 8);
    prep_w_kernel<<<(wt8 + 255) / 256, 256>>>(Q, AM, wt8, K / 8, nblk);

    cudaFuncSetAttribute(gemm_hmma, cudaFuncAttributeMaxDynamicSharedMemorySize, SMEM_B);
    int mtiles = M / BM;
    int ntiles = mtiles * (N / BN);
    int grid = 2 * 148;              // persistent: 2 CTAs per SM
    if (grid > ntiles) grid = ntiles;
    gemm_hmma<<<grid, THREADS, SMEM_B>>>((float*)d_out, M, N, K, ntiles, mtiles);
}

// round 14
// speedup vs baseline: 1.0904x; 1.0751x over previous
#include <cuda_runtime.h>
#include <cuda_fp16.h>
#include <math.h>
#include <stdint.h>

typedef unsigned int u32;

// Fixed dataset shapes: M=4096, K=2048, N=32000
#define MAX_M 4096
#define MAX_K 2048
#define MAX_V 32000

// Static device scratch (allocation-free rule)
__device__ __half g_XH[(size_t)MAX_M * MAX_K];   // x rounded to fp16
__device__ __half g_WD[(size_t)MAX_V * MAX_K];   // dequantized weights in fp16

// ---------------- PTX helpers ----------------

static __device__ __forceinline__ u32 smem_u32(const void* p) {
    u32 a;
    asm("{ .reg .u64 t; cvta.to.shared.u64 t, %1; cvt.u32.u64 %0, t; }"
        : "=r"(a) : "l"(p));
    return a;
}

static __device__ __forceinline__ void cp16(u32 d, const void* g) {
    asm volatile("cp.async.cg.shared.global [%0], [%1], 16;"
                 :: "r"(d), "l"(g) : "memory");
}
static __device__ __forceinline__ void cp_commit() {
    asm volatile("cp.async.commit_group;" ::: "memory");
}
static __device__ __forceinline__ void cp_wait1() {
    asm volatile("cp.async.wait_group 1;" ::: "memory");
}

static __device__ __forceinline__ void ldsm4(u32 a, u32& r0, u32& r1, u32& r2, u32& r3) {
    asm volatile("ldmatrix.sync.aligned.m8n8.x4.shared.b16 {%0,%1,%2,%3}, [%4];"
                 : "=r"(r0), "=r"(r1), "=r"(r2), "=r"(r3) : "r"(a));
}

static __device__ __forceinline__ void mma16816(float* c,
                                                u32 a0, u32 a1, u32 a2, u32 a3,
                                                u32 b0, u32 b1) {
    asm volatile(
        "mma.sync.aligned.m16n8k16.row.col.f32.f16.f16.f32 "
        "{%0,%1,%2,%3}, {%4,%5,%6,%7}, {%8,%9}, {%0,%1,%2,%3};"
        : "+f"(c[0]), "+f"(c[1]), "+f"(c[2]), "+f"(c[3])
        : "r"(a0), "r"(a1), "r"(a2), "r"(a3), "r"(b0), "r"(b1));
}

// Full SW128 swizzle for 128B rows (BK=64 f16): conflict-free STS.128 + ldmatrix.
static __device__ __forceinline__ u32 swz(int row, int chunk) {
    return (u32)(row * 128 + ((chunk ^ (row & 7)) << 4));
}

// ---------------- Pre-pass kernels ----------------

__global__ void prep_x_kernel(const float* __restrict__ X, int total4) {
    int i = blockIdx.x * 256 + threadIdx.x;
    if (i >= total4) return;
    float4 v = ((const float4*)X)[i];
    __half h[4];
    h[0] = __float2half_rn(v.x);
    h[1] = __float2half_rn(v.y);
    h[2] = __float2half_rn(v.z);
    h[3] = __float2half_rn(v.w);
    ((uint2*)g_XH)[i] = *(uint2*)h;
}

// Full dequant: w = (q - 127.5) * absmax/127.5, rounded to fp16. 8 elems/thread.
__global__ void prep_w_kernel(const int* __restrict__ Q,
                              const float* __restrict__ AM,
                              int total8, int kdiv8, int nblk) {
    int i = blockIdx.x * 256 + threadIdx.x;
    if (i >= total8) return;
    int row = i / kdiv8;
    int c8 = i - row * kdiv8;
    int kblk = (c8 * 8) >> 8;
    float s = AM[(size_t)row * nblk + kblk] * (1.0f / 127.5f);
    int4 a = ((const int4*)Q)[2 * i];
    int4 b = ((const int4*)Q)[2 * i + 1];
    __half h[8];
    h[0] = __float2half_rn(((float)a.x - 127.5f) * s);
    h[1] = __float2half_rn(((float)a.y - 127.5f) * s);
    h[2] = __float2half_rn(((float)a.z - 127.5f) * s);
    h[3] = __float2half_rn(((float)a.w - 127.5f) * s);
    h[4] = __float2half_rn(((float)b.x - 127.5f) * s);
    h[5] = __float2half_rn(((float)b.y - 127.5f) * s);
    h[6] = __float2half_rn(((float)b.z - 127.5f) * s);
    h[7] = __float2half_rn(((float)b.w - 127.5f) * s);
    ((uint4*)g_WD)[i] = *(uint4*)h;
}

// ---------------- Main GEMM ----------------
// C[M,N] = X(fp16) * W(fp16)^T, fp32-accumulate HMMA.
// CTA 128x128, BK=64, 4 warps (2m x 2n, 64x64 each), 128 threads,
// 3-stage cp.async, 2 CTAs/SM. Compute ks=0 BEFORE the prefetch burst so
// the post-barrier LSU window is covered by MMAs.

#define BM 128
#define BN 128
#define BK 64
#define THREADS 128
#define TILE_XB (BM * 128)         // 16 KB X [128][64] f16
#define TILE_WB (BN * 128)         // 16 KB W [128][64] f16
#define STAGE_B (TILE_XB + TILE_WB)   // 32 KB
#define NSTAGE 3
#define SMEM_B (NSTAGE * STAGE_B)  // 96 KB

__global__ __launch_bounds__(THREADS, 2)
void gemm_hmma(float* __restrict__ C, int M, int N, int K) {
    extern __shared__ char sm[];
    const u32 sb = smem_u32(sm);
    const int tid = threadIdx.x;
    const int wid = tid >> 5;
    const int lane = tid & 31;
    const int m0 = blockIdx.x * BM;
    const int n0 = blockIdx.y * BN;
    const int warp_m = wid >> 1;      // 0..1 (64 rows each)
    const int warp_n = wid & 1;       // 0..1 (64 cols each)

    const size_t baseX = (size_t)m0 * K;
    const size_t baseW = (size_t)n0 * K;

    // cp.async mapping: 8 threads per 128B row; 16 rows per pass, 8 passes/tile
    const int lrow = tid >> 3;        // 0..15
    const int lchk = tid & 7;         // 0..7

    // A ldmatrix lane decode (x4: m16 x k16 per mi)
    const int matA = lane >> 3;
    const int rowA_base = warp_m * 64 + ((matA & 1) << 3) + (lane & 7);
    const int cA_sel = matA >> 1;
    // B ldmatrix lane decode (x4 covers 2 nj x 2 k-halves)
    const int matB = lane >> 3;
    const int rowB_base = warp_n * 64 + ((matB >> 1) << 3) + (lane & 7);
    const int cB_sel = matB & 1;

    float fin[4][8][4];
#pragma unroll
    for (int i = 0; i < 4; i++)
#pragma unroll
        for (int j = 0; j < 8; j++)
#pragma unroll
            for (int e = 0; e < 4; e++) fin[i][j][e] = 0.0f;

    const int NK = K / BK;   // 32

    // ---- prologue: prefetch stages 0,1 ----
#pragma unroll
    for (int ps = 0; ps < NSTAGE - 1; ps++) {
        const int k0 = ps * BK;
        const u32 st = sb + ps * STAGE_B;
#pragma unroll
        for (int t = 0; t < 8; t++) {
            int row = lrow + t * 16;
            u32 sw = swz(row, lchk);
            size_t gx = baseX + (size_t)row * K + k0 + lchk * 8;
            size_t gw = baseW + (size_t)row * K + k0 + lchk * 8;
            cp16(st + sw, g_XH + gx);
            cp16(st + TILE_XB + sw, g_WD + gw);
        }
        cp_commit();
    }

    for (int kt = 0; kt < NK; kt++) {
        const int s = kt % NSTAGE;

        cp_wait1();           // stage kt landed (in-order group completion)
        __syncthreads();      // stage kt visible; stage kt-1 reads complete

        const u32 stA = sb + s * STAGE_B;
        const u32 stB = stA + TILE_XB;

        // ---- ks = 0 first: cover the post-barrier window with MMAs ----
#pragma unroll
        for (int ks = 0; ks < 1; ks++) {
            u32 bq[8][2];
#pragma unroll
            for (int njp = 0; njp < 4; njp++) {
                u32 off = swz(rowB_base + njp * 16, ks * 2 + cB_sel);
                ldsm4(stB + off, bq[njp * 2][0], bq[njp * 2][1],
                      bq[njp * 2 + 1][0], bq[njp * 2 + 1][1]);
            }
#pragma unroll
            for (int mi = 0; mi < 4; mi++) {
                u32 off = swz(rowA_base + mi * 16, ks * 2 + cA_sel);
                u32 a0, a1, a2, a3;
                ldsm4(stA + off, a0, a1, a2, a3);
#pragma unroll
                for (int nj = 0; nj < 8; nj++)
                    mma16816(fin[mi][nj], a0, a1, a2, a3, bq[nj][0], bq[nj][1]);
            }
        }

        // ---- prefetch stage kt+2 into buffer (kt-1)%3 (reads done pre-sync) ----
        if (kt + NSTAGE - 1 < NK) {
            const int k0 = (kt + NSTAGE - 1) * BK;
            const u32 st = sb + ((kt + NSTAGE - 1) % NSTAGE) * STAGE_B;
#pragma unroll
            for (int t = 0; t < 8; t++) {
                int row = lrow + t * 16;
                u32 sw = swz(row, lchk);
                size_t gx = baseX + (size_t)row * K + k0 + lchk * 8;
                size_t gw = baseW + (size_t)row * K + k0 + lchk * 8;
                cp16(st + sw, g_XH + gx);
                cp16(st + TILE_XB + sw, g_WD + gw);
            }
        }
        cp_commit();          // unconditional: uniform group accounting

        // ---- remaining ks = 1..3 ----
#pragma unroll
        for (int ks = 1; ks < 4; ks++) {
            u32 bq[8][2];
#pragma unroll
            for (int njp = 0; njp < 4; njp++) {
                u32 off = swz(rowB_base + njp * 16, ks * 2 + cB_sel);
                ldsm4(stB + off, bq[njp * 2][0], bq[njp * 2][1],
                      bq[njp * 2 + 1][0], bq[njp * 2 + 1][1]);
            }
#pragma unroll
            for (int mi = 0; mi < 4; mi++) {
                u32 off = swz(rowA_base + mi * 16, ks * 2 + cA_sel);
                u32 a0, a1, a2, a3;
                ldsm4(stA + off, a0, a1, a2, a3);
#pragma unroll
                for (int nj = 0; nj < 8; nj++)
                    mma16816(fin[mi][nj], a0, a1, a2, a3, bq[nj][0], bq[nj][1]);
            }
        }
    }

    // ---- epilogue ----
    const int er = m0 + warp_m * 64 + (lane >> 2);
    const int ec = n0 + warp_n * 64 + (lane & 3) * 2;
#pragma unroll
    for (int mi = 0; mi < 4; mi++) {
#pragma unroll
        for (int nj = 0; nj < 8; nj++) {
            float* p0 = C + (size_t)(er + mi * 16) * N + ec + nj * 8;
            float* p1 = C + (size_t)(er + mi * 16 + 8) * N + ec + nj * 8;
            *(float2*)p0 = make_float2(fin[mi][nj][0], fin[mi][nj][1]);
            *(float2*)p1 = make_float2(fin[mi][nj][2], fin[mi][nj][3]);
        }
    }
}

// ---------------- launch ----------------

extern "C" void kernel_launch(void* const* d_in, const int* in_sizes, int n_in,
                              void* d_out, int out_size) {
    const float* X  = (const float*)d_in[0];
    const int*   Q  = (const int*)d_in[1];
    const float* AM = (const float*)d_in[2];

    double s0 = (double)in_sizes[0];
    double s1 = (double)in_sizes[1];
    double so = (double)out_size;
    int K = (int)(sqrt(s0 * s1 / so) + 0.5);
    int M = (int)(s0 / K + 0.5);
    int N = (int)(s1 / K + 0.5);
    int nblk = K >> 8;

    int xt4 = (M * K) / 4;
    prep_x_kernel<<<(xt4 + 255) / 256, 256>>>(X, xt4);
    int wt8 = (int)(((long long)N * K) / 8);
    prep_w_kernel<<<(wt8 + 255) / 256, 256>>>(Q, AM, wt8, K / 8, nblk);

    cudaFuncSetAttribute(gemm_hmma, cudaFuncAttributeMaxDynamicSharedMemorySize, SMEM_B);
    dim3 grid(M / BM, N / BN);   // m fastest: W n-stripe shared via L2 within a wave
    gemm_hmma<<<grid, THREADS, SMEM_B>>>((float*)d_out, M, N, K);
}

// round 15
// speedup vs baseline: 1.1059x; 1.0141x over previous
#include <cuda_runtime.h>
#include <cuda_fp16.h>
#include <math.h>
#include <stdint.h>

typedef unsigned int u32;

// Fixed dataset shapes: M=4096, K=2048, N=32000
#define MAX_M 4096
#define MAX_K 2048
#define MAX_V 32000

// Static device scratch (allocation-free rule)
__device__ __half g_XH[(size_t)MAX_M * MAX_K];   // x rounded to fp16
__device__ __half g_WD[(size_t)MAX_V * MAX_K];   // dequantized weights in fp16

// ---------------- PTX helpers ----------------

static __device__ __forceinline__ u32 smem_u32(const void* p) {
    u32 a;
    asm("{ .reg .u64 t; cvta.to.shared.u64 t, %1; cvt.u32.u64 %0, t; }"
        : "=r"(a) : "l"(p));
    return a;
}

static __device__ __forceinline__ void cp16(u32 d, const void* g) {
    asm volatile("cp.async.cg.shared.global [%0], [%1], 16;"
                 :: "r"(d), "l"(g) : "memory");
}
static __device__ __forceinline__ void cp_commit() {
    asm volatile("cp.async.commit_group;" ::: "memory");
}
static __device__ __forceinline__ void cp_wait1() {
    asm volatile("cp.async.wait_group 1;" ::: "memory");
}

static __device__ __forceinline__ void ldsm4(u32 a, u32& r0, u32& r1, u32& r2, u32& r3) {
    asm volatile("ldmatrix.sync.aligned.m8n8.x4.shared.b16 {%0,%1,%2,%3}, [%4];"
                 : "=r"(r0), "=r"(r1), "=r"(r2), "=r"(r3) : "r"(a));
}

static __device__ __forceinline__ void mma16816(float* c,
                                                u32 a0, u32 a1, u32 a2, u32 a3,
                                                u32 b0, u32 b1) {
    asm volatile(
        "mma.sync.aligned.m16n8k16.row.col.f32.f16.f16.f32 "
        "{%0,%1,%2,%3}, {%4,%5,%6,%7}, {%8,%9}, {%0,%1,%2,%3};"
        : "+f"(c[0]), "+f"(c[1]), "+f"(c[2]), "+f"(c[3])
        : "r"(a0), "r"(a1), "r"(a2), "r"(a3), "r"(b0), "r"(b1));
}

// Full SW128 swizzle for 128B rows (BK=64 f16): conflict-free STS.128 + ldmatrix.
static __device__ __forceinline__ u32 swz(int row, int chunk) {
    return (u32)(row * 128 + ((chunk ^ (row & 7)) << 4));
}

// ---------------- Pre-pass kernels ----------------

__global__ void prep_x_kernel(const float* __restrict__ X, int total4) {
    int i = blockIdx.x * 256 + threadIdx.x;
    if (i >= total4) return;
    float4 v = ((const float4*)X)[i];
    __half h[4];
    h[0] = __float2half_rn(v.x);
    h[1] = __float2half_rn(v.y);
    h[2] = __float2half_rn(v.z);
    h[3] = __float2half_rn(v.w);
    ((uint2*)g_XH)[i] = *(uint2*)h;
}

// Full dequant: w = (q - 127.5) * absmax/127.5, rounded to fp16. 8 elems/thread.
__global__ void prep_w_kernel(const int* __restrict__ Q,
                              const float* __restrict__ AM,
                              int total8, int kdiv8, int nblk) {
    int i = blockIdx.x * 256 + threadIdx.x;
    if (i >= total8) return;
    int row = i / kdiv8;
    int c8 = i - row * kdiv8;
    int kblk = (c8 * 8) >> 8;
    float s = AM[(size_t)row * nblk + kblk] * (1.0f / 127.5f);
    int4 a = ((const int4*)Q)[2 * i];
    int4 b = ((const int4*)Q)[2 * i + 1];
    __half h[8];
    h[0] = __float2half_rn(((float)a.x - 127.5f) * s);
    h[1] = __float2half_rn(((float)a.y - 127.5f) * s);
    h[2] = __float2half_rn(((float)a.z - 127.5f) * s);
    h[3] = __float2half_rn(((float)a.w - 127.5f) * s);
    h[4] = __float2half_rn(((float)b.x - 127.5f) * s);
    h[5] = __float2half_rn(((float)b.y - 127.5f) * s);
    h[6] = __float2half_rn(((float)b.z - 127.5f) * s);
    h[7] = __float2half_rn(((float)b.w - 127.5f) * s);
    ((uint4*)g_WD)[i] = *(uint4*)h;
}

// ---------------- Main GEMM ----------------
// C[M,N] = X(fp16) * W(fp16)^T, fp32-accumulate HMMA.
// CTA 128x128, BK=64, 4 warps (2m x 2n, 64x64 each), 128 threads,
// 3-stage cp.async, 2 CTAs/SM. Register-level double buffering of
// ldmatrix fragments: load ks+1 frags before issuing ks MMAs.

#define BM 128
#define BN 128
#define BK 64
#define THREADS 128
#define TILE_XB (BM * 128)         // 16 KB X [128][64] f16
#define TILE_WB (BN * 128)         // 16 KB W [128][64] f16
#define STAGE_B (TILE_XB + TILE_WB)   // 32 KB
#define NSTAGE 3
#define SMEM_B (NSTAGE * STAGE_B)  // 96 KB

__global__ __launch_bounds__(THREADS, 2)
void gemm_hmma(float* __restrict__ C, int M, int N, int K) {
    extern __shared__ char sm[];
    const u32 sb = smem_u32(sm);
    const int tid = threadIdx.x;
    const int wid = tid >> 5;
    const int lane = tid & 31;
    const int m0 = blockIdx.x * BM;
    const int n0 = blockIdx.y * BN;
    const int warp_m = wid >> 1;      // 0..1 (64 rows each)
    const int warp_n = wid & 1;       // 0..1 (64 cols each)

    const size_t baseX = (size_t)m0 * K;
    const size_t baseW = (size_t)n0 * K;

    // cp.async mapping: 8 threads per 128B row; 16 rows per pass, 8 passes/tile
    const int lrow = tid >> 3;        // 0..15
    const int lchk = tid & 7;         // 0..7

    // A ldmatrix lane decode (x4: m16 x k16 per mi)
    const int matA = lane >> 3;
    const int rowA_base = warp_m * 64 + ((matA & 1) << 3) + (lane & 7);
    const int cA_sel = matA >> 1;
    // B ldmatrix lane decode (x4 covers 2 nj x 2 k-halves)
    const int matB = lane >> 3;
    const int rowB_base = warp_n * 64 + ((matB >> 1) << 3) + (lane & 7);
    const int cB_sel = matB & 1;

    float fin[4][8][4];
#pragma unroll
    for (int i = 0; i < 4; i++)
#pragma unroll
        for (int j = 0; j < 8; j++)
#pragma unroll
            for (int e = 0; e < 4; e++) fin[i][j][e] = 0.0f;

    const int NK = K / BK;   // 32

    // ---- prologue: prefetch stages 0,1 ----
#pragma unroll
    for (int ps = 0; ps < NSTAGE - 1; ps++) {
        const int k0 = ps * BK;
        const u32 st = sb + ps * STAGE_B;
#pragma unroll
        for (int t = 0; t < 8; t++) {
            int row = lrow + t * 16;
            u32 sw = swz(row, lchk);
            size_t gx = baseX + (size_t)row * K + k0 + lchk * 8;
            size_t gw = baseW + (size_t)row * K + k0 + lchk * 8;
            cp16(st + sw, g_XH + gx);
            cp16(st + TILE_XB + sw, g_WD + gw);
        }
        cp_commit();
    }

    // register fragment double buffers
    u32 aq[2][4][4];
    u32 bq[2][8][2];

    for (int kt = 0; kt < NK; kt++) {
        const int s = kt % NSTAGE;

        cp_wait1();           // stage kt landed (in-order group completion)
        __syncthreads();      // stage kt visible; stage kt-1 reads complete

        // ---- prefetch stage kt+2 into buffer (kt-1)%3 (now safe) ----
        if (kt + NSTAGE - 1 < NK) {
            const int k0 = (kt + NSTAGE - 1) * BK;
            const u32 st = sb + ((kt + NSTAGE - 1) % NSTAGE) * STAGE_B;
#pragma unroll
            for (int t = 0; t < 8; t++) {
                int row = lrow + t * 16;
                u32 sw = swz(row, lchk);
                size_t gx = baseX + (size_t)row * K + k0 + lchk * 8;
                size_t gw = baseW + (size_t)row * K + k0 + lchk * 8;
                cp16(st + sw, g_XH + gx);
                cp16(st + TILE_XB + sw, g_WD + gw);
            }
        }
        cp_commit();          // unconditional: uniform group accounting

        const u32 stA = sb + s * STAGE_B;
        const u32 stB = stA + TILE_XB;

        // ---- load ks=0 fragments into buffer 0 ----
#pragma unroll
        for (int njp = 0; njp < 4; njp++) {
            u32 off = swz(rowB_base + njp * 16, cB_sel);
            ldsm4(stB + off, bq[0][njp * 2][0], bq[0][njp * 2][1],
                  bq[0][njp * 2 + 1][0], bq[0][njp * 2 + 1][1]);
        }
#pragma unroll
        for (int mi = 0; mi < 4; mi++) {
            u32 off = swz(rowA_base + mi * 16, cA_sel);
            ldsm4(stA + off, aq[0][mi][0], aq[0][mi][1], aq[0][mi][2], aq[0][mi][3]);
        }

        // ---- pipelined compute: load ks+1 frags, then MMA ks ----
#pragma unroll
        for (int ks = 0; ks < 4; ks++) {
            const int cur = ks & 1;
            const int nxt = cur ^ 1;
            if (ks < 3) {
#pragma unroll
                for (int njp = 0; njp < 4; njp++) {
                    u32 off = swz(rowB_base + njp * 16, (ks + 1) * 2 + cB_sel);
                    ldsm4(stB + off, bq[nxt][njp * 2][0], bq[nxt][njp * 2][1],
                          bq[nxt][njp * 2 + 1][0], bq[nxt][njp * 2 + 1][1]);
                }
#pragma unroll
                for (int mi = 0; mi < 4; mi++) {
                    u32 off = swz(rowA_base + mi * 16, (ks + 1) * 2 + cA_sel);
                    ldsm4(stA + off, aq[nxt][mi][0], aq[nxt][mi][1],
                          aq[nxt][mi][2], aq[nxt][mi][3]);
                }
            }
#pragma unroll
            for (int mi = 0; mi < 4; mi++)
#pragma unroll
                for (int nj = 0; nj < 8; nj++)
                    mma16816(fin[mi][nj], aq[cur][mi][0], aq[cur][mi][1],
                             aq[cur][mi][2], aq[cur][mi][3],
                             bq[cur][nj][0], bq[cur][nj][1]);
        }
    }

    // ---- epilogue ----
    const int er = m0 + warp_m * 64 + (lane >> 2);
    const int ec = n0 + warp_n * 64 + (lane & 3) * 2;
#pragma unroll
    for (int mi = 0; mi < 4; mi++) {
#pragma unroll
        for (int nj = 0; nj < 8; nj++) {
            float* p0 = C + (size_t)(er + mi * 16) * N + ec + nj * 8;
            float* p1 = C + (size_t)(er + mi * 16 + 8) * N + ec + nj * 8;
            *(float2*)p0 = make_float2(fin[mi][nj][0], fin[mi][nj][1]);
            *(float2*)p1 = make_float2(fin[mi][nj][2], fin[mi][nj][3]);
        }
    }
}

// ---------------- launch ----------------

extern "C" void kernel_launch(void* const* d_in, const int* in_sizes, int n_in,
                              void* d_out, int out_size) {
    const float* X  = (const float*)d_in[0];
    const int*   Q  = (const int*)d_in[1];
    const float* AM = (const float*)d_in[2];

    double s0 = (double)in_sizes[0];
    double s1 = (double)in_sizes[1];
    double so = (double)out_size;
    int K = (int)(sqrt(s0 * s1 / so) + 0.5);
    int M = (int)(s0 / K + 0.5);
    int N = (int)(s1 / K + 0.5);
    int nblk = K >> 8;

    int xt4 = (M * K) / 4;
    prep_x_kernel<<<(xt4 + 255) / 256, 256>>>(X, xt4);
    int wt8 = (int)(((long long)N * K) / 8);
    prep_w_kernel<<<(wt8 + 255) / 256, 256>>>(Q, AM, wt8, K / 8, nblk);

    cudaFuncSetAttribute(gemm_hmma, cudaFuncAttributeMaxDynamicSharedMemorySize, SMEM_B);
    dim3 grid(M / BM, N / BN);   // m fastest: W n-stripe shared via L2 within a wave
    gemm_hmma<<<grid, THREADS, SMEM_B>>>((float*)d_out, M, N, K);
}

// round 16
// speedup vs baseline: 1.1444x; 1.0348x over previous
#include <cuda_runtime.h>
#include <cuda_fp16.h>
#include <math.h>
#include <stdint.h>

typedef unsigned int u32;

// Fixed dataset shapes: M=4096, K=2048, N=32000
#define MAX_M 4096
#define MAX_K 2048
#define MAX_V 32000

// Static device scratch (allocation-free rule)
__device__ __half g_XH[(size_t)MAX_M * MAX_K];   // x rounded to fp16
__device__ __half g_WD[(size_t)MAX_V * MAX_K];   // dequantized weights in fp16

// ---------------- PTX helpers ----------------

static __device__ __forceinline__ u32 smem_u32(const void* p) {
    u32 a;
    asm("{ .reg .u64 t; cvta.to.shared.u64 t, %1; cvt.u32.u64 %0, t; }"
        : "=r"(a) : "l"(p));
    return a;
}

static __device__ __forceinline__ void cp16(u32 d, const void* g) {
    asm volatile("cp.async.cg.shared.global [%0], [%1], 16;"
                 :: "r"(d), "l"(g) : "memory");
}
static __device__ __forceinline__ void cp_commit() {
    asm volatile("cp.async.commit_group;" ::: "memory");
}
static __device__ __forceinline__ void cp_wait1() {
    asm volatile("cp.async.wait_group 1;" ::: "memory");
}

static __device__ __forceinline__ void ldsm4(u32 a, u32& r0, u32& r1, u32& r2, u32& r3) {
    asm volatile("ldmatrix.sync.aligned.m8n8.x4.shared.b16 {%0,%1,%2,%3}, [%4];"
                 : "=r"(r0), "=r"(r1), "=r"(r2), "=r"(r3) : "r"(a));
}

static __device__ __forceinline__ void mma16816(float* c,
                                                u32 a0, u32 a1, u32 a2, u32 a3,
                                                u32 b0, u32 b1) {
    asm volatile(
        "mma.sync.aligned.m16n8k16.row.col.f32.f16.f16.f32 "
        "{%0,%1,%2,%3}, {%4,%5,%6,%7}, {%8,%9}, {%0,%1,%2,%3};"
        : "+f"(c[0]), "+f"(c[1]), "+f"(c[2]), "+f"(c[3])
        : "r"(a0), "r"(a1), "r"(a2), "r"(a3), "r"(b0), "r"(b1));
}

// streaming (evict-first) float2 store
static __device__ __forceinline__ void stcs2(float* p, float x, float y) {
    asm volatile("st.global.cs.v2.f32 [%0], {%1, %2};"
                 :: "l"(p), "f"(x), "f"(y) : "memory");
}

// Full SW128 swizzle for 128B rows (BK=64 f16): conflict-free STS.128 + ldmatrix.
static __device__ __forceinline__ u32 swz(int row, int chunk) {
    return (u32)(row * 128 + ((chunk ^ (row & 7)) << 4));
}

// ---------------- Pre-pass kernels ----------------

__global__ void prep_x_kernel(const float* __restrict__ X, int total4) {
    int i = blockIdx.x * 256 + threadIdx.x;
    if (i >= total4) return;
    float4 v = ((const float4*)X)[i];
    __half h[4];
    h[0] = __float2half_rn(v.x);
    h[1] = __float2half_rn(v.y);
    h[2] = __float2half_rn(v.z);
    h[3] = __float2half_rn(v.w);
    ((uint2*)g_XH)[i] = *(uint2*)h;
}

// Full dequant: w = (q - 127.5) * absmax/127.5, rounded to fp16. 8 elems/thread.
__global__ void prep_w_kernel(const int* __restrict__ Q,
                              const float* __restrict__ AM,
                              int total8, int kdiv8, int nblk) {
    int i = blockIdx.x * 256 + threadIdx.x;
    if (i >= total8) return;
    int row = i / kdiv8;
    int c8 = i - row * kdiv8;
    int kblk = (c8 * 8) >> 8;
    float s = AM[(size_t)row * nblk + kblk] * (1.0f / 127.5f);
    int4 a = ((const int4*)Q)[2 * i];
    int4 b = ((const int4*)Q)[2 * i + 1];
    __half h[8];
    h[0] = __float2half_rn(((float)a.x - 127.5f) * s);
    h[1] = __float2half_rn(((float)a.y - 127.5f) * s);
    h[2] = __float2half_rn(((float)a.z - 127.5f) * s);
    h[3] = __float2half_rn(((float)a.w - 127.5f) * s);
    h[4] = __float2half_rn(((float)b.x - 127.5f) * s);
    h[5] = __float2half_rn(((float)b.y - 127.5f) * s);
    h[6] = __float2half_rn(((float)b.z - 127.5f) * s);
    h[7] = __float2half_rn(((float)b.w - 127.5f) * s);
    ((uint4*)g_WD)[i] = *(uint4*)h;
}

// ---------------- Main GEMM ----------------
// C[M,N] = X(fp16) * W(fp16)^T, fp32-accumulate HMMA.
// CTA 128x128, BK=64, 4 warps (2m x 2n, 64x64 each), 128 threads,
// 3-stage cp.async, 2 CTAs/SM. k-loop unrolled by 3 so stage bases are
// compile-time constants (no modulo in the critical path).

#define BM 128
#define BN 128
#define BK 64
#define THREADS 128
#define TILE_XB (BM * 128)         // 16 KB X [128][64] f16
#define TILE_WB (BN * 128)         // 16 KB W [128][64] f16
#define STAGE_B (TILE_XB + TILE_WB)   // 32 KB
#define NSTAGE 3
#define SMEM_B (NSTAGE * STAGE_B)  // 96 KB

struct KtCtx {
    u32 sb;
    size_t baseX, baseW;
    int K, NK;
    int lrow, lchk;
    int rowA_base, cA_sel, rowB_base, cB_sel;
};

// One k-iteration; stage offsets are call-site constants after inlining.
static __device__ __forceinline__ void kt_step(
    const KtCtx& c, int kt, u32 offCur, u32 offPre, float fin[4][8][4])
{
    cp_wait1();           // stage kt landed (in-order group completion)
    __syncthreads();      // stage kt visible; stage kt-1 reads complete

    // ---- prefetch stage kt+2 into buffer offPre (reads done pre-sync) ----
    if (kt + NSTAGE - 1 < c.NK) {
        const int k0 = (kt + NSTAGE - 1) * BK;
        const u32 st = c.sb + offPre;
        const __half* gx0 = g_XH + c.baseX + (size_t)c.lrow * c.K + k0 + c.lchk * 8;
        const __half* gw0 = g_WD + c.baseW + (size_t)c.lrow * c.K + k0 + c.lchk * 8;
#pragma unroll
        for (int t = 0; t < 8; t++) {
            int row = c.lrow + t * 16;
            u32 sw = swz(row, c.lchk);
            cp16(st + sw, gx0 + (size_t)t * 16 * c.K);
            cp16(st + TILE_XB + sw, gw0 + (size_t)t * 16 * c.K);
        }
    }
    cp_commit();          // unconditional: uniform group accounting

    // ---- compute stage offCur: 4 k16 sub-steps ----
    const u32 stA = c.sb + offCur;
    const u32 stB = stA + TILE_XB;

#pragma unroll
    for (int ks = 0; ks < 4; ks++) {
        u32 bq[8][2];
#pragma unroll
        for (int njp = 0; njp < 4; njp++) {
            u32 off = swz(c.rowB_base + njp * 16, ks * 2 + c.cB_sel);
            ldsm4(stB + off, bq[njp * 2][0], bq[njp * 2][1],
                  bq[njp * 2 + 1][0], bq[njp * 2 + 1][1]);
        }
#pragma unroll
        for (int mi = 0; mi < 4; mi++) {
            u32 off = swz(c.rowA_base + mi * 16, ks * 2 + c.cA_sel);
            u32 a0, a1, a2, a3;
            ldsm4(stA + off, a0, a1, a2, a3);
#pragma unroll
            for (int nj = 0; nj < 8; nj++)
                mma16816(fin[mi][nj], a0, a1, a2, a3, bq[nj][0], bq[nj][1]);
        }
    }
}

__global__ __launch_bounds__(THREADS, 2)
void gemm_hmma(float* __restrict__ C, int M, int N, int K) {
    extern __shared__ char sm[];
    const int tid = threadIdx.x;
    const int wid = tid >> 5;
    const int lane = tid & 31;
    const int m0 = blockIdx.x * BM;
    const int n0 = blockIdx.y * BN;
    const int warp_m = wid >> 1;      // 0..1 (64 rows each)
    const int warp_n = wid & 1;       // 0..1 (64 cols each)

    KtCtx c;
    c.sb = smem_u32(sm);
    c.baseX = (size_t)m0 * K;
    c.baseW = (size_t)n0 * K;
    c.K = K;
    c.NK = K / BK;                    // 32
    c.lrow = tid >> 3;                // 0..15
    c.lchk = tid & 7;                 // 0..7
    {
        const int matA = lane >> 3;
        c.rowA_base = warp_m * 64 + ((matA & 1) << 3) + (lane & 7);
        c.cA_sel = matA >> 1;
        const int matB = lane >> 3;
        c.rowB_base = warp_n * 64 + ((matB >> 1) << 3) + (lane & 7);
        c.cB_sel = matB & 1;
    }

    float fin[4][8][4];
#pragma unroll
    for (int i = 0; i < 4; i++)
#pragma unroll
        for (int j = 0; j < 8; j++)
#pragma unroll
            for (int e = 0; e < 4; e++) fin[i][j][e] = 0.0f;

    // ---- prologue: prefetch stages 0,1 ----
#pragma unroll
    for (int ps = 0; ps < NSTAGE - 1; ps++) {
        const int k0 = ps * BK;
        const u32 st = c.sb + ps * STAGE_B;
#pragma unroll
        for (int t = 0; t < 8; t++) {
            int row = c.lrow + t * 16;
            u32 sw = swz(row, c.lchk);
            size_t gx = c.baseX + (size_t)row * K + k0 + c.lchk * 8;
            size_t gw = c.baseW + (size_t)row * K + k0 + c.lchk * 8;
            cp16(st + sw, g_XH + gx);
            cp16(st + TILE_XB + sw, g_WD + gw);
        }
        cp_commit();
    }

    // ---- main loop unrolled by NSTAGE: stage bases are constants ----
    int kt = 0;
    for (; kt + NSTAGE <= c.NK; kt += NSTAGE) {
        kt_step(c, kt,     0 * STAGE_B, 2 * STAGE_B, fin);
        kt_step(c, kt + 1, 1 * STAGE_B, 0 * STAGE_B, fin);
        kt_step(c, kt + 2, 2 * STAGE_B, 1 * STAGE_B, fin);
    }
    if (kt < c.NK) { kt_step(c, kt, 0 * STAGE_B, 2 * STAGE_B, fin); kt++; }
    if (kt < c.NK) { kt_step(c, kt, 1 * STAGE_B, 0 * STAGE_B, fin); }

    // ---- epilogue: streaming stores (C is write-once; keep L2 for W) ----
    const int er = m0 + warp_m * 64 + (lane >> 2);
    const int ec = n0 + warp_n * 64 + (lane & 3) * 2;
#pragma unroll
    for (int mi = 0; mi < 4; mi++) {
#pragma unroll
        for (int nj = 0; nj < 8; nj++) {
            float* p0 = C + (size_t)(er + mi * 16) * N + ec + nj * 8;
            float* p1 = C + (size_t)(er + mi * 16 + 8) * N + ec + nj * 8;
            stcs2(p0, fin[mi][nj][0], fin[mi][nj][1]);
            stcs2(p1, fin[mi][nj][2], fin[mi][nj][3]);
        }
    }
}

// ---------------- launch ----------------

extern "C" void kernel_launch(void* const* d_in, const int* in_sizes, int n_in,
                              void* d_out, int out_size) {
    const float* X  = (const float*)d_in[0];
    const int*   Q  = (const int*)d_in[1];
    const float* AM = (const float*)d_in[2];

    double s0 = (double)in_sizes[0];
    double s1 = (double)in_sizes[1];
    double so = (double)out_size;
    int K = (int)(sqrt(s0 * s1 / so) + 0.5);
    int M = (int)(s0 / K + 0.5);
    int N = (int)(s1 / K + 0.5);
    int nblk = K >> 8;

    int xt4 = (M * K) / 4;
    prep_x_kernel<<<(xt4 + 255) / 256, 256>>>(X, xt4);
    int wt8 = (int)(((long long)N * K) / 8);
    prep_w_kernel<<<(wt8 + 255) / 256, 256>>>(Q, AM, wt8, K / 8, nblk);

    cudaFuncSetAttribute(gemm_hmma, cudaFuncAttributeMaxDynamicSharedMemorySize, SMEM_B);
    dim3 grid(M / BM, N / BN);   // m fastest: W n-stripe shared via L2 within a wave
    gemm_hmma<<<grid, THREADS, SMEM_B>>>((float*)d_out, M, N, K);
}